// round 10
// baseline (speedup 1.0000x reference)
#include <cuda_runtime.h>
#include <cuda_bf16.h>
#include <cstdint>

#define NUM_GRIDS 8

__device__ __forceinline__ float tanh_approx(float x) {
    float y;
    asm("tanh.approx.f32 %0, %1;" : "=f"(y) : "f"(x));
    return y;
}

__device__ __forceinline__ float bump(float xi, float g) {
    const float th = tanh_approx(xi - g);
    return 1.0f - th * th;
}

__device__ __forceinline__ void stg256(float* dst,
                                       float r0, float r1, float r2, float r3,
                                       float r4, float r5, float r6, float r7) {
    asm volatile(
        "st.global.cs.v8.f32 [%0], {%1,%2,%3,%4,%5,%6,%7,%8};"
        :: "l"(dst),
           "f"(r0), "f"(r1), "f"(r2), "f"(r3),
           "f"(r4), "f"(r5), "f"(r6), "f"(r7)
        : "memory");
}

// Persistent grid-stride kernel: 592 CTAs = exactly 4/SM on 148 SMs.
// Per iteration: 1x LDG.64 (warp = 256 B contiguous), 16 outputs via
// 2x STG.256 (warp = 2 KB contiguous). Unroll-2 loop lets ptxas hoist the
// next iteration's independent load above this iteration's stores,
// pipelining load latency against store drain within each warp.
__global__ __launch_bounds__(256)
void rswaf_kernel(const float2* __restrict__ x,
                  const float4* __restrict__ grid,   // [8] floats = 2 float4
                  const float*  __restrict__ inv_den,
                  float*        __restrict__ out,
                  int n2) {
    const float inv = __ldg(inv_den);

    // pre-scale grid by inv: (x-g)*inv = x*inv - g*inv
    const float4 gA = __ldg(grid + 0);
    const float4 gB = __ldg(grid + 1);
    const float g0 = gA.x * inv, g1 = gA.y * inv, g2 = gA.z * inv, g3 = gA.w * inv;
    const float g4 = gB.x * inv, g5 = gB.y * inv, g6 = gB.z * inv, g7 = gB.w * inv;

    const int stride = gridDim.x * blockDim.x;

#pragma unroll 2
    for (int i = blockIdx.x * blockDim.x + threadIdx.x; i < n2; i += stride) {
        const float2 xv = __ldcs(x + i);
        const float xa = xv.x * inv;
        const float xb = xv.y * inv;

        float* dst = out + (long long)i * (2 * NUM_GRIDS);

        stg256(dst,
               bump(xa, g0), bump(xa, g1), bump(xa, g2), bump(xa, g3),
               bump(xa, g4), bump(xa, g5), bump(xa, g6), bump(xa, g7));

        stg256(dst + NUM_GRIDS,
               bump(xb, g0), bump(xb, g1), bump(xb, g2), bump(xb, g3),
               bump(xb, g4), bump(xb, g5), bump(xb, g6), bump(xb, g7));
    }
}

extern "C" void kernel_launch(void* const* d_in, const int* in_sizes, int n_in,
                              void* d_out, int out_size) {
    const float* x       = (const float*)d_in[0];   // [16,64,128,128] fp32
    const float* grid    = (const float*)d_in[1];   // [8] fp32
    const float* inv_den = (const float*)d_in[2];   // scalar fp32
    float* out = (float*)d_out;                     // [...,8] fp32

    const int n  = in_sizes[0];        // 16,777,216 (even)
    const int n2 = n >> 1;             // 8,388,608 float2s

    const int threads = 256;
    const int blocks  = 592;           // 148 SMs x 4 CTAs (32 warps/SM), persistent

    rswaf_kernel<<<blocks, threads>>>(
        (const float2*)x, (const float4*)grid, inv_den, out, n2);
}